// round 4
// baseline (speedup 1.0000x reference)
#include <cuda_runtime.h>
#include <cstdint>

// ---------------- problem constants ----------------
#define B_SZ   2048
#define IN_F   1024
#define N_C    64
#define E_SZ   128
#define O_SZ   256
#define TM     128
#define KT     32
#define NCHUNK (IN_F / KT)   // 32
#define SLOPE  0.01f
#define LDA    36            // padded smem row (floats) -> conflict-free LDS.128
#define LDB    36

// ---------------- scratch (static device globals) ----------------
__device__ float g_Xt[B_SZ * IN_F];                     // tf32-rounded, k-permuted
__device__ float g_Wt[(size_t)N_C * O_SZ * IN_F];       // [n][o][k] tf32, k-permuted

// ---------------- helpers ----------------
__device__ __forceinline__ uint32_t smem_u32(const void* p) {
    uint32_t a;
    asm("{ .reg .u64 t; cvta.to.shared.u64 t, %1; cvt.u32.u64 %0, t; }" : "=r"(a) : "l"(p));
    return a;
}
__device__ __forceinline__ float to_tf32(float x) {
    uint32_t u; asm("cvt.rna.tf32.f32 %0, %1;" : "=r"(u) : "f"(x));
    return __uint_as_float(u);
}
__device__ __forceinline__ void cp16(uint32_t dst, const void* src) {
    asm volatile("cp.async.cg.shared.global [%0], [%1], 16;" :: "r"(dst), "l"(src) : "memory");
}
__device__ __forceinline__ void lds4(uint32_t addr, uint32_t& x, uint32_t& y,
                                     uint32_t& z, uint32_t& w) {
    asm volatile("ld.shared.v4.b32 {%0,%1,%2,%3}, [%4];"
                 : "=r"(x), "=r"(y), "=r"(z), "=r"(w) : "r"(addr));
}
__device__ __forceinline__ void mma_tf32(float* d, uint32_t a0, uint32_t a1,
                                         uint32_t a2, uint32_t a3,
                                         uint32_t b0, uint32_t b1) {
    asm volatile(
        "mma.sync.aligned.m16n8k8.row.col.f32.tf32.tf32.f32 "
        "{%0,%1,%2,%3}, {%4,%5,%6,%7}, {%8,%9}, {%0,%1,%2,%3};"
        : "+f"(d[0]), "+f"(d[1]), "+f"(d[2]), "+f"(d[3])
        : "r"(a0), "r"(a1), "r"(a2), "r"(a3), "r"(b0), "r"(b1));
}

// ---------------- fused prep kernel ----------------
// z == 64  : X tf32-round + k-permute  (256 blocks' worth of work, 1 chunk/thread)
// z <  64  : W transpose [n][k][o] -> [n][o][kperm] + tf32 round
// k-permutation within each aligned 32-block: position p holds k = (p>>3) + 4*(p&7),
// so each thread's fragment across 4 k8-steps is 8 contiguous floats.
__global__ void conv_prep(const float* __restrict__ x, const float* __restrict__ W) {
    const int tx = threadIdx.x, ty = threadIdx.y;   // 32 x 8
    if (blockIdx.z == 64) {
        const int c = (blockIdx.y * 32 + blockIdx.x) * 256 + ty * 32 + tx;
        const float4* src = reinterpret_cast<const float4*>(x) + (size_t)c * 8;
        float v[32];
#pragma unroll
        for (int f = 0; f < 8; ++f) {
            float4 t = src[f];
            v[4*f] = t.x; v[4*f+1] = t.y; v[4*f+2] = t.z; v[4*f+3] = t.w;
        }
        float o[32];
#pragma unroll
        for (int p = 0; p < 32; ++p) o[p] = to_tf32(v[(p >> 3) + 4 * (p & 7)]);
        float4* dst = reinterpret_cast<float4*>(g_Xt) + (size_t)c * 8;
#pragma unroll
        for (int f = 0; f < 8; ++f)
            dst[f] = make_float4(o[4*f], o[4*f+1], o[4*f+2], o[4*f+3]);
        return;
    }
    __shared__ float tile[32][33];
    const int n = blockIdx.z, k0 = blockIdx.x * 32, o0 = blockIdx.y * 32;
    const float* src = W + ((size_t)n * IN_F + k0) * O_SZ + o0;
#pragma unroll
    for (int i = 0; i < 4; ++i)
        tile[ty + 8*i][tx] = src[(size_t)(ty + 8*i) * O_SZ + tx];
    __syncthreads();
    const int kp = k0 + (tx & 3) * 8 + (tx >> 2);   // permuted position for k=tx
    const size_t base = (size_t)n * O_SZ + o0;
#pragma unroll
    for (int i = 0; i < 4; ++i) {
        const int o = ty + 8*i;
        g_Wt[(base + o) * IN_F + kp] = to_tf32(tile[tx][o]);
    }
}

// ---------------- GEMM + fused epilogue ----------------
// 256 threads = 8 warps as 2M x 4N, warp tile 64x64, CTA tile 128x256.
// dyn smem: double buffer { A 128x36 (18432B), B 256x36 (36864B) } = 2x55296
//           epilogue overlay: nctx[128][132] at 0; sdot[128][4] at 110592; pv at 112640
#define BUF_BYTES  55296
#define B_OFF      18432
#define SD_OFF     110592
#define PV_OFF     112640
#define SMEM_TOTAL 113664

__global__ __launch_bounds__(256, 1)
void concept_mma_kernel(const float* __restrict__ bc,
                        const float* __restrict__ wp,
                        const float* __restrict__ bp,
                        float* __restrict__ out)
{
    extern __shared__ char smem[];
    const uint32_t sb = smem_u32(smem);
    const int tid = threadIdx.x, lane = tid & 31, wid = tid >> 5;
    const int wn = wid & 3, wm = wid >> 2;     // 4 N-warps x 2 M-warps
    const int n = blockIdx.y, m0 = blockIdx.x * TM;

    const float* Ag = g_Xt + (size_t)m0 * IN_F;
    const float* Bg = g_Wt + (size_t)n * O_SZ * IN_F;

    float acc[4][8][4];
#pragma unroll
    for (int a = 0; a < 4; ++a)
#pragma unroll
        for (int b = 0; b < 8; ++b)
#pragma unroll
            for (int c = 0; c < 4; ++c) acc[a][b][c] = 0.f;

    // copies: A tile = 1024 x 16B (4/thread), B tile = 2048 x 16B (8/thread)
    const int arow = tid >> 3, aseg = tid & 7;       // rows step by 32
    // ---- prologue: chunk 0 ----
    {
        const uint32_t ab = sb, bb = sb + B_OFF;
#pragma unroll
        for (int j = 0; j < 4; ++j)
            cp16(ab + ((arow + 32*j) * LDA + aseg * 4) * 4,
                 Ag + (size_t)(arow + 32*j) * IN_F + aseg * 4);
#pragma unroll
        for (int j = 0; j < 8; ++j)
            cp16(bb + ((arow + 32*j) * LDB + aseg * 4) * 4,
                 Bg + (size_t)(arow + 32*j) * IN_F + aseg * 4);
        asm volatile("cp.async.commit_group;" ::: "memory");
        asm volatile("cp.async.wait_group 0;" ::: "memory");
        __syncthreads();
    }

    for (int t = 0; t < NCHUNK; ++t) {
        if (t + 1 < NCHUNK) {   // prefetch next chunk into other buffer
            const uint32_t ab = sb + ((t + 1) & 1) * BUF_BYTES, bb = ab + B_OFF;
            const float* An = Ag + (t + 1) * KT;
            const float* Bn = Bg + (t + 1) * KT;
#pragma unroll
            for (int j = 0; j < 4; ++j)
                cp16(ab + ((arow + 32*j) * LDA + aseg * 4) * 4,
                     An + (size_t)(arow + 32*j) * IN_F + aseg * 4);
#pragma unroll
            for (int j = 0; j < 8; ++j)
                cp16(bb + ((arow + 32*j) * LDB + aseg * 4) * 4,
                     Bn + (size_t)(arow + 32*j) * IN_F + aseg * 4);
            asm volatile("cp.async.commit_group;" ::: "memory");
        }

        const uint32_t ab = sb + (t & 1) * BUF_BYTES, bb = ab + B_OFF;
#pragma unroll
        for (int h = 0; h < 2; ++h) {                // k8 steps {2h, 2h+1}
            uint32_t bf[8][4];
#pragma unroll
            for (int nt = 0; nt < 8; ++nt) {
                const int nrow = wn * 64 + nt * 8 + (lane >> 2);
                lds4(bb + (nrow * LDB + (lane & 3) * 8 + h * 4) * 4,
                     bf[nt][0], bf[nt][1], bf[nt][2], bf[nt][3]);
            }
#pragma unroll
            for (int mt = 0; mt < 4; ++mt) {
                const int r0 = wm * 64 + mt * 16 + (lane >> 2);
                uint32_t a0[4], a1[4];
                lds4(ab + (r0 * LDA + (lane & 3) * 8 + h * 4) * 4,
                     a0[0], a0[1], a0[2], a0[3]);
                lds4(ab + ((r0 + 8) * LDA + (lane & 3) * 8 + h * 4) * 4,
                     a1[0], a1[1], a1[2], a1[3]);
#pragma unroll
                for (int g = 0; g < 2; ++g) {
#pragma unroll
                    for (int nt = 0; nt < 8; ++nt)
                        mma_tf32(acc[mt][nt],
                                 a0[2*g], a1[2*g], a0[2*g+1], a1[2*g+1],
                                 bf[nt][2*g], bf[nt][2*g+1]);
                }
            }
        }
        asm volatile("cp.async.wait_group 0;" ::: "memory");
        __syncthreads();
    }

    // ---------------- fused epilogue ----------------
    const float* bcn = bc + (size_t)n * O_SZ;
    float* nctx = reinterpret_cast<float*>(smem);               // [128][132]
    float* sdot = reinterpret_cast<float*>(smem + SD_OFF);      // [128][4]
    float* pv   = reinterpret_cast<float*>(smem + PV_OFF);      // [128]

    float dotr[4][2] = {{0.f, 0.f}, {0.f, 0.f}, {0.f, 0.f}, {0.f, 0.f}};
#pragma unroll
    for (int mt = 0; mt < 4; ++mt) {
#pragma unroll
        for (int nt = 0; nt < 8; ++nt) {
            const int colb = wn * 64 + nt * 8 + 2 * (lane & 3);
            const float b0v = bcn[colb], b1v = bcn[colb + 1];
            const float w0 = wp[colb],  w1 = wp[colb + 1];
#pragma unroll
            for (int rr = 0; rr < 2; ++rr) {
                float v0 = acc[mt][nt][2*rr]     + b0v;
                float v1 = acc[mt][nt][2*rr + 1] + b1v;
                v0 = (v0 >= 0.f) ? v0 : SLOPE * v0;
                v1 = (v1 >= 0.f) ? v1 : SLOPE * v1;
                acc[mt][nt][2*rr] = v0; acc[mt][nt][2*rr + 1] = v1;
                dotr[mt][rr] = fmaf(v0, w0, fmaf(v1, w1, dotr[mt][rr]));
            }
        }
    }
#pragma unroll
    for (int mt = 0; mt < 4; ++mt)
#pragma unroll
        for (int rr = 0; rr < 2; ++rr) {
            dotr[mt][rr] += __shfl_xor_sync(0xffffffffu, dotr[mt][rr], 1);
            dotr[mt][rr] += __shfl_xor_sync(0xffffffffu, dotr[mt][rr], 2);
        }
    if ((lane & 3) == 0) {
#pragma unroll
        for (int mt = 0; mt < 4; ++mt)
#pragma unroll
            for (int rr = 0; rr < 2; ++rr) {
                const int row = wm * 64 + mt * 16 + (lane >> 2) + 8 * rr;
                sdot[row * 4 + wn] = dotr[mt][rr];
            }
    }
    if (wn >= 2) {   // stage negative half (cols 128..255) for the blend
#pragma unroll
        for (int mt = 0; mt < 4; ++mt)
#pragma unroll
            for (int nt = 0; nt < 8; ++nt) {
                const int row = wm * 64 + mt * 16 + (lane >> 2);
                const int col = (wn - 2) * 64 + nt * 8 + 2 * (lane & 3);
                nctx[row * 132 + col]           = acc[mt][nt][0];
                nctx[row * 132 + col + 1]       = acc[mt][nt][1];
                nctx[(row + 8) * 132 + col]     = acc[mt][nt][2];
                nctx[(row + 8) * 132 + col + 1] = acc[mt][nt][3];
            }
    }
    __syncthreads();

    if (tid < 128) {
        const float s = sdot[tid * 4] + sdot[tid * 4 + 1]
                      + sdot[tid * 4 + 2] + sdot[tid * 4 + 3];
        const float p = 1.f / (1.f + expf(-(s + *bp)));
        pv[tid] = p;
        out[(size_t)B_SZ * N_C * E_SZ + (size_t)(m0 + tid) * N_C + n] = p;
    }
    __syncthreads();

    if (wn < 2) {    // blend + store c_emb (cols 0..127)
#pragma unroll
        for (int mt = 0; mt < 4; ++mt) {
#pragma unroll
            for (int rr = 0; rr < 2; ++rr) {
                const int row = wm * 64 + mt * 16 + (lane >> 2) + 8 * rr;
                const float p = pv[row];
                float* orow = out + ((size_t)(m0 + row) * N_C + n) * E_SZ;
#pragma unroll
                for (int nt = 0; nt < 8; ++nt) {
                    const int col = wn * 64 + nt * 8 + 2 * (lane & 3);
                    const float p0 = acc[mt][nt][2*rr], p1 = acc[mt][nt][2*rr + 1];
                    const float g0 = nctx[row * 132 + col];
                    const float g1 = nctx[row * 132 + col + 1];
                    *reinterpret_cast<float2*>(orow + col) =
                        make_float2(fmaf(p0 - g0, p, g0), fmaf(p1 - g1, p, g1));
                }
            }
        }
    }
}

// ---------------- launch ----------------
extern "C" void kernel_launch(void* const* d_in, const int* in_sizes, int n_in,
                              void* d_out, int out_size)
{
    const float* x  = (const float*)d_in[0];   // [2048,1024]
    const float* Wc = (const float*)d_in[1];   // [64,1024,256]
    const float* bc = (const float*)d_in[2];   // [64,256]
    const float* wp = (const float*)d_in[3];   // [256]
    const float* bp = (const float*)d_in[4];   // scalar
    float* out = (float*)d_out;

    cudaFuncSetAttribute(concept_mma_kernel,
                         cudaFuncAttributeMaxDynamicSharedMemorySize, SMEM_TOTAL);

    conv_prep<<<dim3(32, 8, 65), dim3(32, 8)>>>(x, Wc);
    concept_mma_kernel<<<dim3(B_SZ / TM, N_C), 256, SMEM_TOTAL>>>(bc, wp, bp, out);
}

// round 5
// speedup vs baseline: 2.0149x; 2.0149x over previous
#include <cuda_runtime.h>
#include <cuda_fp16.h>
#include <cstdint>

// ---------------- problem constants ----------------
#define B_SZ   2048
#define IN_F   1024
#define N_C    64
#define E_SZ   128
#define O_SZ   256
#define TM     128
#define KT     64            // fp16 k per chunk -> 128B rows
#define NCHUNK (IN_F / KT)   // 16
#define SLOPE  0.01f

// ---------------- scratch (static device globals) ----------------
__device__ __half g_Xh[B_SZ * IN_F];                    // fp16, k-permuted
__device__ __half g_Wh[(size_t)N_C * O_SZ * IN_F];      // [n][o][k] fp16, k-permuted

// ---------------- helpers ----------------
__device__ __forceinline__ uint32_t smem_u32(const void* p) {
    uint32_t a;
    asm("{ .reg .u64 t; cvta.to.shared.u64 t, %1; cvt.u32.u64 %0, t; }" : "=r"(a) : "l"(p));
    return a;
}
__device__ __forceinline__ void cp16(uint32_t dst, const void* src) {
    asm volatile("cp.async.cg.shared.global [%0], [%1], 16;" :: "r"(dst), "l"(src) : "memory");
}
__device__ __forceinline__ void lds4(uint32_t addr, uint32_t& x, uint32_t& y,
                                     uint32_t& z, uint32_t& w) {
    asm volatile("ld.shared.v4.b32 {%0,%1,%2,%3}, [%4];"
                 : "=r"(x), "=r"(y), "=r"(z), "=r"(w) : "r"(addr));
}
__device__ __forceinline__ void mma_f16(float* d, uint32_t a0, uint32_t a1,
                                        uint32_t a2, uint32_t a3,
                                        uint32_t b0, uint32_t b1) {
    asm volatile(
        "mma.sync.aligned.m16n8k16.row.col.f32.f16.f16.f32 "
        "{%0,%1,%2,%3}, {%4,%5,%6,%7}, {%8,%9}, {%0,%1,%2,%3};"
        : "+f"(d[0]), "+f"(d[1]), "+f"(d[2]), "+f"(d[3])
        : "r"(a0), "r"(a1), "r"(a2), "r"(a3), "r"(b0), "r"(b1));
}

// smem tile addressing: 128B rows, 8 x 16B segs, 1-bit XOR swizzle on seg bit2
// (makes odd rows use the other 64B half -> conflict-free quarter-warp phases)
__device__ __forceinline__ uint32_t tile_off(int row, int seg) {
    return (uint32_t)(row * 128 + ((seg ^ ((row & 1) << 2)) << 4));
}

// ---------------- fused prep kernel ----------------
// k-permutation within each aligned 32-block: position p holds
// k = 16*s + 8*w + 2*q + e  where p = q*8 + s*4 + w*2 + e.
// Then 16B segment q of a 32-block is exactly the m16n8k16 fragment data for
// thread-group q (two k16 steps), so every fragment fetch is one LDS.128.
__global__ void conv_prep(const float* __restrict__ x, const float* __restrict__ W) {
    const int tx = threadIdx.x, ty = threadIdx.y;   // 32 x 8
    if (blockIdx.z == 64) {
        // X: one 32-k block per thread
        const int c = (blockIdx.y * 32 + blockIdx.x) * 256 + ty * 32 + tx;
        const float4* src = reinterpret_cast<const float4*>(x) + (size_t)c * 8;
        float v[32];
#pragma unroll
        for (int f = 0; f < 8; ++f) {
            float4 t = src[f];
            v[4*f] = t.x; v[4*f+1] = t.y; v[4*f+2] = t.z; v[4*f+3] = t.w;
        }
        __half o[32];
#pragma unroll
        for (int p = 0; p < 32; ++p) {
            const int k = 16 * ((p >> 2) & 1) + 8 * ((p >> 1) & 1)
                        + 2 * (p >> 3) + (p & 1);
            o[p] = __float2half_rn(v[k]);
        }
        uint4* dst = reinterpret_cast<uint4*>(g_Xh + (size_t)c * 32);
#pragma unroll
        for (int f = 0; f < 4; ++f)
            dst[f] = reinterpret_cast<const uint4*>(o)[f];
        return;
    }
    // W: transpose [n][k][o] -> [n][o][kperm] + fp16
    __shared__ float tile[32][33];
    const int n = blockIdx.z, k0 = blockIdx.x * 32, o0 = blockIdx.y * 32;
    const float* src = W + ((size_t)n * IN_F + k0) * O_SZ + o0;
#pragma unroll
    for (int i = 0; i < 4; ++i)
        tile[ty + 8*i][tx] = src[(size_t)(ty + 8*i) * O_SZ + tx];
    __syncthreads();
    // write phase: 256 threads = 32 o x 8 (q,half) units, 8B (4 fp16) each
    const int u = ty * 32 + tx;
    const int o = u >> 3, s8 = u & 7;
    const int q = s8 & 3, half = s8 >> 2;
    const int kb = 16 * half + 2 * q;   // k-list: kb, kb+1, kb+8, kb+9
    __half hv[4];
    hv[0] = __float2half_rn(tile[kb][o]);
    hv[1] = __float2half_rn(tile[kb + 1][o]);
    hv[2] = __float2half_rn(tile[kb + 8][o]);
    hv[3] = __float2half_rn(tile[kb + 9][o]);
    __half* drow = g_Wh + ((size_t)n * O_SZ + o0 + o) * IN_F + k0 + q * 8 + half * 4;
    *reinterpret_cast<uint2*>(drow) = *reinterpret_cast<const uint2*>(hv);
}

// ---------------- GEMM + fused epilogue ----------------
// 256 threads = 8 warps as 2M x 4N, warp tile 64x64, CTA tile 128x256.
// dyn smem: double buffer { A 128x128B (16K), B 256x128B (32K) } = 2 x 48K
//           epilogue overlay: nctx[128][132] at 0; sdot at 98304; pv at 100352
#define A_BYTES    16384
#define BUF_BYTES  49152
#define SD_OFF     98304
#define PV_OFF     100352
#define SMEM_TOTAL 100864

__global__ __launch_bounds__(256, 1)
void concept_mma_kernel(const float* __restrict__ bc,
                        const float* __restrict__ wp,
                        const float* __restrict__ bp,
                        float* __restrict__ out)
{
    extern __shared__ char smem[];
    const uint32_t sb = smem_u32(smem);
    const int tid = threadIdx.x, lane = tid & 31, wid = tid >> 5;
    const int wn = wid & 3, wm = wid >> 2;     // 4 N-warps x 2 M-warps
    const int n = blockIdx.y, m0 = blockIdx.x * TM;
    const int lq = lane & 3, lr = lane >> 2;

    const __half* Ag = g_Xh + (size_t)m0 * IN_F;
    const __half* Bg = g_Wh + (size_t)n * O_SZ * IN_F;

    float acc[4][8][4];
#pragma unroll
    for (int a = 0; a < 4; ++a)
#pragma unroll
        for (int b = 0; b < 8; ++b)
#pragma unroll
            for (int c = 0; c < 4; ++c) acc[a][b][c] = 0.f;

    // copies per chunk: A = 1024 x 16B (4/thread), B = 2048 x 16B (8/thread)
    // ---- prologue: chunk 0 ----
    {
        const uint32_t ab = sb, bb = sb + A_BYTES;
#pragma unroll
        for (int j = 0; j < 4; ++j) {
            const int idx = tid + 256 * j, row = idx >> 3, seg = idx & 7;
            cp16(ab + tile_off(row, seg), Ag + (size_t)row * IN_F + seg * 8);
        }
#pragma unroll
        for (int j = 0; j < 8; ++j) {
            const int idx = tid + 256 * j, row = idx >> 3, seg = idx & 7;
            cp16(bb + tile_off(row, seg), Bg + (size_t)row * IN_F + seg * 8);
        }
        asm volatile("cp.async.commit_group;" ::: "memory");
        asm volatile("cp.async.wait_group 0;" ::: "memory");
        __syncthreads();
    }

    for (int t = 0; t < NCHUNK; ++t) {
        if (t + 1 < NCHUNK) {   // prefetch next chunk into other buffer
            const uint32_t ab = sb + ((t + 1) & 1) * BUF_BYTES, bb = ab + A_BYTES;
            const __half* An = Ag + (t + 1) * KT;
            const __half* Bn = Bg + (t + 1) * KT;
#pragma unroll
            for (int j = 0; j < 4; ++j) {
                const int idx = tid + 256 * j, row = idx >> 3, seg = idx & 7;
                cp16(ab + tile_off(row, seg), An + (size_t)row * IN_F + seg * 8);
            }
#pragma unroll
            for (int j = 0; j < 8; ++j) {
                const int idx = tid + 256 * j, row = idx >> 3, seg = idx & 7;
                cp16(bb + tile_off(row, seg), Bn + (size_t)row * IN_F + seg * 8);
            }
            asm volatile("cp.async.commit_group;" ::: "memory");
        }

        const uint32_t ab = sb + (t & 1) * BUF_BYTES, bb = ab + A_BYTES;
#pragma unroll
        for (int blk = 0; blk < 2; ++blk) {     // two 32-k blocks (= 2 k16 steps each)
            const int seg = blk * 4 + lq;
            uint32_t bf[8][4];
#pragma unroll
            for (int nt = 0; nt < 8; ++nt) {
                const int nrow = wn * 64 + nt * 8 + lr;
                lds4(bb + tile_off(nrow, seg), bf[nt][0], bf[nt][1], bf[nt][2], bf[nt][3]);
            }
#pragma unroll
            for (int mt = 0; mt < 4; ++mt) {
                const int r0 = wm * 64 + mt * 16 + lr;
                uint32_t aLo[4], aHi[4];
                lds4(ab + tile_off(r0, seg),     aLo[0], aLo[1], aLo[2], aLo[3]);
                lds4(ab + tile_off(r0 + 8, seg), aHi[0], aHi[1], aHi[2], aHi[3]);
#pragma unroll
                for (int s = 0; s < 2; ++s) {
#pragma unroll
                    for (int nt = 0; nt < 8; ++nt)
                        mma_f16(acc[mt][nt],
                                aLo[2*s], aHi[2*s], aLo[2*s+1], aHi[2*s+1],
                                bf[nt][2*s], bf[nt][2*s+1]);
                }
            }
        }
        asm volatile("cp.async.wait_group 0;" ::: "memory");
        __syncthreads();
    }

    // ---------------- fused epilogue ----------------
    const float* bcn = bc + (size_t)n * O_SZ;
    float* nctx = reinterpret_cast<float*>(smem);               // [128][132]
    float* sdot = reinterpret_cast<float*>(smem + SD_OFF);      // [128][4]
    float* pv   = reinterpret_cast<float*>(smem + PV_OFF);      // [128]

    float dotr[4][2] = {{0.f, 0.f}, {0.f, 0.f}, {0.f, 0.f}, {0.f, 0.f}};
#pragma unroll
    for (int mt = 0; mt < 4; ++mt) {
#pragma unroll
        for (int nt = 0; nt < 8; ++nt) {
            const int colb = wn * 64 + nt * 8 + 2 * lq;
            const float b0v = bcn[colb], b1v = bcn[colb + 1];
            const float w0 = wp[colb],  w1 = wp[colb + 1];
#pragma unroll
            for (int rr = 0; rr < 2; ++rr) {
                float v0 = acc[mt][nt][2*rr]     + b0v;
                float v1 = acc[mt][nt][2*rr + 1] + b1v;
                v0 = (v0 >= 0.f) ? v0 : SLOPE * v0;
                v1 = (v1 >= 0.f) ? v1 : SLOPE * v1;
                acc[mt][nt][2*rr] = v0; acc[mt][nt][2*rr + 1] = v1;
                dotr[mt][rr] = fmaf(v0, w0, fmaf(v1, w1, dotr[mt][rr]));
            }
        }
    }
#pragma unroll
    for (int mt = 0; mt < 4; ++mt)
#pragma unroll
        for (int rr = 0; rr < 2; ++rr) {
            dotr[mt][rr] += __shfl_xor_sync(0xffffffffu, dotr[mt][rr], 1);
            dotr[mt][rr] += __shfl_xor_sync(0xffffffffu, dotr[mt][rr], 2);
        }
    if (lq == 0) {
#pragma unroll
        for (int mt = 0; mt < 4; ++mt)
#pragma unroll
            for (int rr = 0; rr < 2; ++rr) {
                const int row = wm * 64 + mt * 16 + lr + 8 * rr;
                sdot[row * 4 + wn] = dotr[mt][rr];
            }
    }
    if (wn >= 2) {   // stage negative half (cols 128..255) for the blend
#pragma unroll
        for (int mt = 0; mt < 4; ++mt)
#pragma unroll
            for (int nt = 0; nt < 8; ++nt) {
                const int row = wm * 64 + mt * 16 + lr;
                const int col = (wn - 2) * 64 + nt * 8 + 2 * lq;
                nctx[row * 132 + col]           = acc[mt][nt][0];
                nctx[row * 132 + col + 1]       = acc[mt][nt][1];
                nctx[(row + 8) * 132 + col]     = acc[mt][nt][2];
                nctx[(row + 8) * 132 + col + 1] = acc[mt][nt][3];
            }
    }
    __syncthreads();

    if (tid < 128) {
        const float s = sdot[tid * 4] + sdot[tid * 4 + 1]
                      + sdot[tid * 4 + 2] + sdot[tid * 4 + 3];
        const float p = 1.f / (1.f + expf(-(s + *bp)));
        pv[tid] = p;
        out[(size_t)B_SZ * N_C * E_SZ + (size_t)(m0 + tid) * N_C + n] = p;
    }
    __syncthreads();

    if (wn < 2) {    // blend + store c_emb (cols 0..127)
#pragma unroll
        for (int mt = 0; mt < 4; ++mt) {
#pragma unroll
            for (int rr = 0; rr < 2; ++rr) {
                const int row = wm * 64 + mt * 16 + lr + 8 * rr;
                const float p = pv[row];
                float* orow = out + ((size_t)(m0 + row) * N_C + n) * E_SZ;
#pragma unroll
                for (int nt = 0; nt < 8; ++nt) {
                    const int col = wn * 64 + nt * 8 + 2 * lq;
                    const float p0 = acc[mt][nt][2*rr], p1 = acc[mt][nt][2*rr + 1];
                    const float g0 = nctx[row * 132 + col];
                    const float g1 = nctx[row * 132 + col + 1];
                    *reinterpret_cast<float2*>(orow + col) =
                        make_float2(fmaf(p0 - g0, p, g0), fmaf(p1 - g1, p, g1));
                }
            }
        }
    }
}

// ---------------- launch ----------------
extern "C" void kernel_launch(void* const* d_in, const int* in_sizes, int n_in,
                              void* d_out, int out_size)
{
    const float* x  = (const float*)d_in[0];   // [2048,1024]
    const float* Wc = (const float*)d_in[1];   // [64,1024,256]
    const float* bc = (const float*)d_in[2];   // [64,256]
    const float* wp = (const float*)d_in[3];   // [256]
    const float* bp = (const float*)d_in[4];   // scalar
    float* out = (float*)d_out;

    cudaFuncSetAttribute(concept_mma_kernel,
                         cudaFuncAttributeMaxDynamicSharedMemorySize, SMEM_TOTAL);

    conv_prep<<<dim3(32, 8, 65), dim3(32, 8)>>>(x, Wc);
    concept_mma_kernel<<<dim3(B_SZ / TM, N_C), 256, SMEM_TOTAL>>>(bc, wp, bp, out);
}